// round 17
// baseline (speedup 1.0000x reference)
#include <cuda_runtime.h>
#include <cuda_bf16.h>
#include <math.h>
#include <stdint.h>

#define B 64
#define T 512
#define E 256
#define H 200
#define G4 800   // 4*H
#define C 20
#define LN_EPS 1e-5f

typedef unsigned long long ull;

// LSTM cluster config
#define UPC 50          // hidden units per CTA (4 CTAs/cluster -> 200)
#define NBATCH 4        // batches per cluster
#define SEG 25          // k per segment (8 segments cover H=200)
#define SEGP 36         // padded seg stride in h rows
#define HROW (8 * SEGP) // 288 floats per (buf, batch) h row

// GEMM (bf16 tensor-core) config
#define GMT 128
#define GNT 64
#define GSM_A (GMT * 512)              // 65536 B (128 rows x 256 bf16)
#define GSM_B (GNT * 512)              // 32768 B
#define GEMM_SMEM_B16 (GSM_A + GSM_B)  // 98304 B

// ---------------- scratch (device globals; no allocation) ----------------
__device__ unsigned short d_xb[(size_t)B * T * E];   // bf16 LN'd embeddings
__device__ unsigned short d_wb[(size_t)2 * G4 * E];  // bf16 w_ih (both dirs)
__device__ float d_g0[(size_t)B * T * G4];
__device__ float d_g1[(size_t)B * T * G4];
__device__ float d_hf[(size_t)B * T * H];
__device__ float d_hb[(size_t)B * T * H];
__device__ float d_logits[(size_t)B * T * C];
__device__ float d_loss[B];
__device__ float d_wt[2 * H * G4];   // [dir][unit j][gate g][k]

__device__ __forceinline__ float tanh_ap(float x) {
    float y;
    asm("tanh.approx.f32 %0, %1;" : "=f"(y) : "f"(x));
    return y;
}
__device__ __forceinline__ float fsigm(float x) {
    return fmaf(0.5f, tanh_ap(0.5f * x), 0.5f);
}
__device__ __forceinline__ float ftanh(float x) {
    return tanh_ap(x);
}
__device__ __forceinline__ ull ffma2(ull a, ull b, ull c) {
    ull d;
    asm("fma.rn.f32x2 %0, %1, %2, %3;" : "=l"(d) : "l"(a), "l"(b), "l"(c));
    return d;
}
__device__ __forceinline__ float2 uf2(ull u) {
    float2 f;
    f.x = __uint_as_float((unsigned)(u & 0xffffffffu));
    f.y = __uint_as_float((unsigned)(u >> 32));
    return f;
}
__device__ __forceinline__ ull packf2(float lo, float hi) {
    return (ull)__float_as_uint(lo) | ((ull)__float_as_uint(hi) << 32);
}
__device__ __forceinline__ void cluster_sync_() {
    asm volatile("barrier.cluster.arrive.aligned;" ::: "memory");
    asm volatile("barrier.cluster.wait.aligned;" ::: "memory");
}
__device__ __forceinline__ void cluster_arrive_() {
    asm volatile("barrier.cluster.arrive.aligned;" ::: "memory");
}
__device__ __forceinline__ void cluster_wait_() {
    asm volatile("barrier.cluster.wait.aligned;" ::: "memory");
}
__device__ __forceinline__ void st_shared_cluster(uint32_t laddr, int rank, float v) {
    uint32_t raddr;
    asm volatile("mapa.shared::cluster.u32 %0, %1, %2;" : "=r"(raddr) : "r"(laddr), "r"(rank));
    asm volatile("st.shared::cluster.f32 [%0], %1;" :: "r"(raddr), "f"(v) : "memory");
}

// ---------------- 0a) permute w_hh -> [dir][j][g][k] ----------------
__global__ void transpose_whh(const float* __restrict__ whf,
                              const float* __restrict__ whb) {
    int idx = blockIdx.x * blockDim.x + threadIdx.x;
    if (idx >= 2 * H * G4) return;
    int dir = idx / (H * G4);
    int r = idx % (H * G4);
    int j = r / G4;
    int rr = r % G4;
    int g = rr / H;
    int k = rr % H;
    const float* W = dir ? whb : whf;
    d_wt[idx] = W[(size_t)(g * H + j) * H + k];
}

// ---------------- 0b) convert w_ih to bf16 ----------------
__global__ void conv_wih(const float* __restrict__ wf, const float* __restrict__ wb) {
    int i = blockIdx.x * 256 + threadIdx.x;
    if (i < G4 * E) {
        __nv_bfloat16 a = __float2bfloat16(wf[i]);
        __nv_bfloat16 b = __float2bfloat16(wb[i]);
        d_wb[i] = *(unsigned short*)&a;
        d_wb[G4 * E + i] = *(unsigned short*)&b;
    }
}

// ---------------- 1) embedding + layernorm (writes bf16) ----------------
__global__ void embed_ln_kernel(const int* __restrict__ words,
                                const float* __restrict__ emb,
                                const float* __restrict__ gamma,
                                const float* __restrict__ beta) {
    int tok = blockIdx.x;
    int e = threadIdx.x;
    int lane = e & 31, w = e >> 5;
    int wd = words[tok];
    float v = emb[(size_t)wd * E + e];

    float s1 = v, s2 = v * v;
    #pragma unroll
    for (int o = 16; o > 0; o >>= 1) {
        s1 += __shfl_down_sync(0xffffffffu, s1, o);
        s2 += __shfl_down_sync(0xffffffffu, s2, o);
    }
    __shared__ float a1[8], a2[8];
    __shared__ float mu_s, rs_s;
    if (lane == 0) { a1[w] = s1; a2[w] = s2; }
    __syncthreads();
    if (e == 0) {
        float t1 = 0.f, t2 = 0.f;
        #pragma unroll
        for (int i = 0; i < 8; i++) { t1 += a1[i]; t2 += a2[i]; }
        float mu = t1 * (1.0f / E);
        float var = t2 * (1.0f / E) - mu * mu;
        mu_s = mu;
        rs_s = rsqrtf(var + LN_EPS);
    }
    __syncthreads();
    float xv = (v - mu_s) * rs_s * gamma[e] + beta[e];
    __nv_bfloat16 xb = __float2bfloat16(xv);
    d_xb[(size_t)tok * E + e] = *(unsigned short*)&xb;
}

// ---------------- 2) input GEMM: bf16 tensor cores (m16n8k16) ----------------
// gates[m,n] = sum_k x[m,k]*W[n,k] + bias[n]. Whole K=256 staged in smem.
// 16B-chunk XOR swizzle slot = c ^ (row & 7): conflict-free STS.128 + ldmatrix.
__global__ void __launch_bounds__(256)
gates_gemm_bf16(const float* __restrict__ b_f, const float* __restrict__ b_b) {
    extern __shared__ char gsm[];
    char* Asm = gsm;
    char* Bsm = gsm + GSM_A;

    int dir = blockIdx.z;
    const unsigned short* Wb = d_wb + (size_t)dir * G4 * E;
    const float* bias = dir ? b_b : b_f;
    float* out = dir ? d_g1 : d_g0;

    int m0 = blockIdx.y * GMT;
    int n0 = blockIdx.x * GNT;
    int tid = threadIdx.x;

    // stage A: 128 rows x 32 chunks (16B each)
    {
        const uint4* src = (const uint4*)(d_xb + (size_t)m0 * E);
        #pragma unroll
        for (int i = 0; i < 16; i++) {
            int id = tid + i * 256;
            int m = id >> 5, c = id & 31;
            uint4 v = src[m * 32 + c];
            *(uint4*)(Asm + m * 512 + ((c ^ (m & 7)) << 4)) = v;
        }
        #pragma unroll
        for (int i = 0; i < 8; i++) {
            int id = tid + i * 256;
            int n = id >> 5, c = id & 31;
            int gn = n0 + n;
            uint4 v = make_uint4(0u, 0u, 0u, 0u);
            if (gn < G4) v = *(const uint4*)(Wb + (size_t)gn * E + c * 8);
            *(uint4*)(Bsm + n * 512 + ((c ^ (n & 7)) << 4)) = v;
        }
    }
    __syncthreads();

    int wid = tid >> 5, lane = tid & 31;
    int wm = wid & 3, wn = wid >> 2;     // 4 m-tiles x 2 n-tiles of 32
    int mb = wm * 32, nb = wn * 32;
    int sub = lane >> 3, tr = lane & 7;

    uint32_t asm_base = (uint32_t)__cvta_generic_to_shared(Asm);
    uint32_t bsm_base = (uint32_t)__cvta_generic_to_shared(Bsm);

    float acc[2][4][4];
    #pragma unroll
    for (int i = 0; i < 2; i++)
        #pragma unroll
        for (int j = 0; j < 4; j++)
            #pragma unroll
            for (int r = 0; r < 4; r++) acc[i][j][r] = 0.f;

    #pragma unroll
    for (int kk = 0; kk < 16; kk++) {
        int cl = 2 * kk + (sub >> 1);        // 16B chunk index for this lane
        uint32_t a[2][4];
        #pragma unroll
        for (int mt = 0; mt < 2; mt++) {
            int ml = mb + mt * 16 + (sub & 1) * 8 + tr;
            uint32_t ad = asm_base + ml * 512 + ((cl ^ (ml & 7)) << 4);
            asm volatile("ldmatrix.sync.aligned.m8n8.x4.shared.b16 {%0,%1,%2,%3}, [%4];"
                : "=r"(a[mt][0]), "=r"(a[mt][1]), "=r"(a[mt][2]), "=r"(a[mt][3])
                : "r"(ad));
        }
        uint32_t bf[4][2];
        #pragma unroll
        for (int bt = 0; bt < 2; bt++) {
            int nl = nb + bt * 16 + (sub & 1) * 8 + tr;
            uint32_t ad = bsm_base + nl * 512 + ((cl ^ (nl & 7)) << 4);
            uint32_t r0, r1, r2, r3;
            asm volatile("ldmatrix.sync.aligned.m8n8.x4.shared.b16 {%0,%1,%2,%3}, [%4];"
                : "=r"(r0), "=r"(r1), "=r"(r2), "=r"(r3) : "r"(ad));
            bf[2 * bt][0] = r0; bf[2 * bt + 1][0] = r1;
            bf[2 * bt][1] = r2; bf[2 * bt + 1][1] = r3;
        }
        #pragma unroll
        for (int mt = 0; mt < 2; mt++)
            #pragma unroll
            for (int nt = 0; nt < 4; nt++) {
                asm volatile(
                    "mma.sync.aligned.m16n8k16.row.col.f32.bf16.bf16.f32 "
                    "{%0,%1,%2,%3}, {%4,%5,%6,%7}, {%8,%9}, {%0,%1,%2,%3};"
                    : "+f"(acc[mt][nt][0]), "+f"(acc[mt][nt][1]),
                      "+f"(acc[mt][nt][2]), "+f"(acc[mt][nt][3])
                    : "r"(a[mt][0]), "r"(a[mt][1]), "r"(a[mt][2]), "r"(a[mt][3]),
                      "r"(bf[nt][0]), "r"(bf[nt][1]));
            }
    }

    // epilogue: c0,c1 at (row, col..col+1); c2,c3 at (row+8, ...)
    #pragma unroll
    for (int mt = 0; mt < 2; mt++) {
        int row = m0 + mb + mt * 16 + (lane >> 2);
        #pragma unroll
        for (int nt = 0; nt < 4; nt++) {
            int col = n0 + nb + nt * 8 + 2 * (lane & 3);
            if (col < G4) {
                float b0 = bias[col], b1 = bias[col + 1];
                *(float2*)(out + (size_t)row * G4 + col) =
                    make_float2(acc[mt][nt][0] + b0, acc[mt][nt][1] + b1);
                *(float2*)(out + (size_t)(row + 8) * G4 + col) =
                    make_float2(acc[mt][nt][2] + b0, acc[mt][nt][3] + b1);
            }
        }
    }
}

// ---------------- 3) LSTM: register weights, 4-CTA cluster, split barrier ----------------
__global__ void __cluster_dims__(4, 1, 1) __launch_bounds__(400, 1)
lstm_cluster_kernel(const int* __restrict__ seq_len) {
    __shared__ __align__(16) float hbuf[2][NBATCH][HROW];

    int cid = blockIdx.x >> 2;
    uint32_t rank;
    asm("mov.u32 %0, %%cluster_ctarank;" : "=r"(rank));
    int dir = cid & 1;
    int grp = cid >> 1;
    int tid = threadIdx.x;
    int jl = tid >> 3;
    int ks = tid & 7;
    int jg = rank * UPC + jl;

    const float* gates = dir ? d_g1 : d_g0;
    float* hs = dir ? d_hb : d_hf;

    // weights into registers: wreg[g][p] = (W[k0+2p], W[k0+2p+1])
    ull wreg[4][13];
    {
        const float* wb = d_wt + (size_t)(dir * H + jg) * G4;   // [g][k]
        int k0 = ks * SEG;
        #pragma unroll
        for (int g = 0; g < 4; g++) {
            #pragma unroll
            for (int p = 0; p < 13; p++) {
                float lo = wb[g * H + k0 + 2 * p];
                float hi = (2 * p + 1 < SEG) ? wb[g * H + k0 + 2 * p + 1] : 0.f;
                wreg[g][p] = packf2(lo, hi);
            }
        }
    }
    for (int i = tid; i < 2 * NBATCH * HROW; i += 400) ((float*)hbuf)[i] = 0.f;

    bool owner = (ks < NBATCH);
    int bg = grp * NBATCH + (ks & 3);
    int L = seq_len[bg];
    float ckeep = 0.f, hkeep = 0.f;
    int hseg = jg / SEG, hoff = jg % SEG;

    // prefetch gates for step 0
    float ngi = 0.f, ngf = 0.f, ngg = 0.f, ngo = 0.f;
    {
        int t0 = dir ? (T - 1) : 0;
        if (owner) {
            const float* gp = gates + ((size_t)bg * T + t0) * G4;
            ngi = gp[jg]; ngf = gp[H + jg]; ngg = gp[2 * H + jg]; ngo = gp[3 * H + jg];
        }
    }

    cluster_sync_();   // zeroed h visible cluster-wide

    for (int s = 0; s < T; s++) {
        int t = dir ? (T - 1 - s) : s;
        int cur = s & 1, nxt = cur ^ 1;
        float gi = ngi, gf = ngf, gg = ngg, go = ngo;

        float ai = 0.f, af = 0.f, ag = 0.f, ao = 0.f;
        #pragma unroll
        for (int b = 0; b < NBATCH; b++) {
            const float* hr = &hbuf[cur][b][ks * SEGP];
            ull a0 = 0, a1 = 0, a2 = 0, a3 = 0;
            #pragma unroll
            for (int q = 0; q < 6; q++) {
                ulonglong2 h2 = *(const ulonglong2*)(hr + 4 * q);
                a0 = ffma2(wreg[0][2 * q], h2.x, a0);
                a1 = ffma2(wreg[1][2 * q], h2.x, a1);
                a2 = ffma2(wreg[2][2 * q], h2.x, a2);
                a3 = ffma2(wreg[3][2 * q], h2.x, a3);
                a0 = ffma2(wreg[0][2 * q + 1], h2.y, a0);
                a1 = ffma2(wreg[1][2 * q + 1], h2.y, a1);
                a2 = ffma2(wreg[2][2 * q + 1], h2.y, a2);
                a3 = ffma2(wreg[3][2 * q + 1], h2.y, a3);
            }
            {
                ull hl = *(const ull*)(hr + 24);   // pair 12 (k 24, pad)
                a0 = ffma2(wreg[0][12], hl, a0);
                a1 = ffma2(wreg[1][12], hl, a1);
                a2 = ffma2(wreg[2][12], hl, a2);
                a3 = ffma2(wreg[3][12], hl, a3);
            }
            float2 v;
            v = uf2(a0); float r0 = v.x + v.y;
            v = uf2(a1); float r1 = v.x + v.y;
            v = uf2(a2); float r2 = v.x + v.y;
            v = uf2(a3); float r3 = v.x + v.y;
            #pragma unroll
            for (int o = 1; o < 8; o <<= 1) {
                r0 += __shfl_xor_sync(0xffffffffu, r0, o);
                r1 += __shfl_xor_sync(0xffffffffu, r1, o);
                r2 += __shfl_xor_sync(0xffffffffu, r2, o);
                r3 += __shfl_xor_sync(0xffffffffu, r3, o);
            }
            if (ks == b) { ai = r0; af = r1; ag = r2; ao = r3; }
        }

        if (owner) {
            float igt = fsigm(ai + gi);
            float fgt = fsigm(af + gf);
            float ogt = fsigm(ao + go);
            float cn = fgt * ckeep + igt * ftanh(ag + gg);
            float hn = ogt * ftanh(cn);
            bool m = (t < L);
            float hv = m ? hn : hkeep;
            ckeep = m ? cn : ckeep;
            hkeep = hv;

            uint32_t laddr = (uint32_t)__cvta_generic_to_shared(
                &hbuf[nxt][ks][hseg * SEGP + hoff]);
            st_shared_cluster(laddr, 0, hv);
            st_shared_cluster(laddr, 1, hv);
            st_shared_cluster(laddr, 2, hv);
            st_shared_cluster(laddr, 3, hv);

            hs[((size_t)bg * T + t) * H + jg] = hv;
        }

        cluster_arrive_();   // release our h stores
        if (s + 1 < T) {
            int t2 = dir ? (T - 2 - s) : (s + 1);
            if (owner) {
                const float* gp = gates + ((size_t)bg * T + t2) * G4;
                ngi = gp[jg]; ngf = gp[H + jg]; ngg = gp[2 * H + jg]; ngo = gp[3 * H + jg];
            }
        }
        cluster_wait_();
    }
}

// ---------------- 4) FC + log-softmax ----------------
#define FTOK 8
__global__ void fc_ls_kernel(const float* __restrict__ fcw, const float* __restrict__ fcb) {
    __shared__ float shw[2 * H * C];
    __shared__ float shh[FTOK][2 * H];
    __shared__ float sfeat[FTOK][C];
    __shared__ float slse[FTOK];

    int tid = threadIdx.x;
    int tt = tid / C;
    int c = tid % C;
    int tok0 = blockIdx.x * FTOK;

    for (int idx = tid; idx < 2 * H * C; idx += FTOK * C) {
        int cc = idx / (2 * H);
        int k = idx % (2 * H);
        shw[k * C + cc] = fcw[idx];
    }
    for (int idx = tid; idx < FTOK * 2 * H; idx += FTOK * C) {
        int t = idx / (2 * H);
        int k = idx % (2 * H);
        size_t tok = tok0 + t;
        shh[t][k] = (k < H) ? d_hf[tok * H + k] : d_hb[tok * H + (k - H)];
    }
    __syncthreads();

    float acc = fcb[c];
    const float* hrow = shh[tt];
    #pragma unroll 8
    for (int k = 0; k < 2 * H; k++)
        acc += hrow[k] * shw[k * C + c];
    sfeat[tt][c] = acc;
    __syncthreads();

    if (c == 0) {
        float m = sfeat[tt][0];
        #pragma unroll
        for (int i = 1; i < C; i++) m = fmaxf(m, sfeat[tt][i]);
        float ssum = 0.f;
        #pragma unroll
        for (int i = 0; i < C; i++) ssum += __expf(sfeat[tt][i] - m);
        slse[tt] = m + __logf(ssum);
    }
    __syncthreads();
    d_logits[(size_t)(tok0 + tt) * C + c] = acc - slse[tt];
}

// ---------------- 5) CRF NLL (one warp per batch) ----------------
__global__ void crf_kernel(const int* __restrict__ target,
                           const int* __restrict__ seq_len,
                           const float* __restrict__ trans,
                           const float* __restrict__ sv,
                           const float* __restrict__ ev) {
    int b = blockIdx.x;
    int tid = threadIdx.x;
    __shared__ float tr[C * C];
    __shared__ float alpha[C];

    for (int i = tid; i < C * C; i += 32) tr[i] = trans[i];
    int L = seq_len[b];
    const int* tgt = target + (size_t)b * T;
    const float* lg = d_logits + (size_t)b * T * C;

    float acc = 0.f;
    for (int t = tid; t < L; t += 32) acc += lg[(size_t)t * C + tgt[t]];
    for (int t = 1 + tid; t < L; t += 32) acc += trans[tgt[t - 1] * C + tgt[t]];
    #pragma unroll
    for (int o = 16; o > 0; o >>= 1) acc += __shfl_down_sync(0xffffffffu, acc, o);

    __syncwarp();
    if (tid < C) alpha[tid] = sv[tid] + lg[tid];
    __syncwarp();

    float trcol[C];
    if (tid < C) {
        #pragma unroll
        for (int c1 = 0; c1 < C; c1++) trcol[c1] = tr[c1 * C + tid];
    }

    for (int t = 1; t < L; t++) {
        float na = 0.f;
        if (tid < C) {
            float v[C];
            #pragma unroll
            for (int c1 = 0; c1 < C; c1++) v[c1] = alpha[c1] + trcol[c1];
            float mx[C];
            #pragma unroll
            for (int c1 = 0; c1 < C; c1++) mx[c1] = v[c1];
            #pragma unroll
            for (int st = 1; st < C; st *= 2)
                #pragma unroll
                for (int i = 0; i + st < C; i += 2 * st) mx[i] = fmaxf(mx[i], mx[i + st]);
            float m = mx[0];
            #pragma unroll
            for (int c1 = 0; c1 < C; c1++) v[c1] = __expf(v[c1] - m);
            #pragma unroll
            for (int st = 1; st < C; st *= 2)
                #pragma unroll
                for (int i = 0; i + st < C; i += 2 * st) v[i] += v[i + st];
            na = m + __logf(v[0]) + lg[(size_t)t * C + tid];
        }
        __syncwarp();
        if (tid < C) alpha[tid] = na;
        __syncwarp();
    }

    if (tid == 0) {
        float m = -1e30f;
        #pragma unroll
        for (int c = 0; c < C; c++) m = fmaxf(m, alpha[c] + ev[c]);
        float ssum = 0.f;
        #pragma unroll
        for (int c = 0; c < C; c++) ssum += __expf(alpha[c] + ev[c] - m);
        float logZ = m + __logf(ssum);
        float gold = acc + sv[tgt[0]] + ev[tgt[L - 1]];
        d_loss[b] = logZ - gold;
    }
}

// ---------------- 6) mean ----------------
__global__ void mean_kernel(float* __restrict__ out) {
    int tid = threadIdx.x;
    __shared__ float red[B];
    red[tid] = d_loss[tid];
    __syncthreads();
    #pragma unroll
    for (int s = 32; s > 0; s >>= 1) {
        if (tid < s) red[tid] += red[tid + s];
        __syncthreads();
    }
    if (tid == 0) out[0] = red[0] * (1.0f / B);
}

// ---------------- launch ----------------
extern "C" void kernel_launch(void* const* d_in, const int* in_sizes, int n_in,
                              void* d_out, int out_size) {
    const int* words    = (const int*)d_in[0];
    const int* seq_len  = (const int*)d_in[1];
    const int* target   = (const int*)d_in[2];
    const float* embed  = (const float*)d_in[3];
    const float* gamma  = (const float*)d_in[4];
    const float* beta   = (const float*)d_in[5];
    const float* wihf   = (const float*)d_in[6];
    const float* whhf   = (const float*)d_in[7];
    const float* bf     = (const float*)d_in[8];
    const float* wihb   = (const float*)d_in[9];
    const float* whhb   = (const float*)d_in[10];
    const float* bb     = (const float*)d_in[11];
    const float* fcw    = (const float*)d_in[12];
    const float* fcb    = (const float*)d_in[13];
    const float* trans  = (const float*)d_in[14];
    const float* sv     = (const float*)d_in[15];
    const float* ev     = (const float*)d_in[16];
    float* out = (float*)d_out;

    cudaFuncSetAttribute(gates_gemm_bf16,
                         cudaFuncAttributeMaxDynamicSharedMemorySize, GEMM_SMEM_B16);

    transpose_whh<<<(2 * H * G4 + 255) / 256, 256>>>(whhf, whhb);
    conv_wih<<<(G4 * E + 255) / 256, 256>>>(wihf, wihb);

    embed_ln_kernel<<<B * T, 256>>>(words, embed, gamma, beta);

    dim3 ggrid((G4 + GNT - 1) / GNT, (B * T) / GMT, 2);
    gates_gemm_bf16<<<ggrid, 256, GEMM_SMEM_B16>>>(bf, bb);

    lstm_cluster_kernel<<<128, 400>>>(seq_len);

    fc_ls_kernel<<<(B * T) / FTOK, FTOK * C>>>(fcw, fcb);

    crf_kernel<<<B, 32>>>(target, seq_len, trans, sv, ev);

    mean_kernel<<<1, B>>>(out);
}